// round 1
// baseline (speedup 1.0000x reference)
#include <cuda_runtime.h>
#include <cstdint>

// Problem constants
#define NB    32
#define LL    1568
#define DD    768
#define HEADS 12
#define PARTS 49
#define DH    64
#define ROWS  (NB * LL)          // 50176
#define GROUPS (ROWS / PARTS)    // 1024
#define SCALE 0.125f

// Scratch (static device globals -- no dynamic allocation)
__device__ float g_kv[(size_t)ROWS * 1536];   // [row][0:768]=k_gathered, [768:1536]=v_gathered
__device__ float g_att[(size_t)ROWS * DD];    // attention output (pre-projection)
__device__ int   g_rowoff[ROWS];              // gathered A-row offsets (in floats) into x
__device__ int   g_is64;

// ---------------------------------------------------------------------------
// shuffle_ids dtype probe: if int64, the odd 32-bit words (high halves) are 0.
__global__ void detect_idx_kernel(const void* sid) {
    const unsigned* p = (const unsigned*)sid;
    int nz = 0;
    for (int i = 1; i < 2048; i += 2) nz += (p[i] != 0u);
    g_is64 = (nz == 0) ? 1 : 0;
}

__global__ void rowoff_kernel(const void* sid) {
    int r = blockIdx.x * 256 + threadIdx.x;
    if (r >= ROWS) return;
    int id;
    if (g_is64) id = (int)((const long long*)sid)[r];
    else        id = ((const int*)sid)[r];
    int n = r / LL;
    g_rowoff[r] = (n * LL + id) * DD;
}

// ---------------------------------------------------------------------------
// NT SGEMM: C[M,N] = A_rows @ B^T (+bias). A rows optionally gathered via rowoff.
// A logical row r has K contiguous floats at A + roff[r].
// B is [N,K] row-major (K contiguous) -> we read it K-contiguous too.
#define BM 128
#define BN 128
#define BK 8
#define TM 8
#define TN 8

__global__ void __launch_bounds__(256)
sgemm_nt(const float* __restrict__ A, const int* __restrict__ rowoff,
         const float* __restrict__ B, const float* __restrict__ bias,
         float* __restrict__ C, int K, int ldc)
{
    __shared__ float As[BK][BM];
    __shared__ float Bs[BK][BN];
    __shared__ int   roff[BM];

    const int t  = threadIdx.x;
    const int bm = blockIdx.y * BM;
    const int bn = blockIdx.x * BN;

    if (t < BM) {
        int r = bm + t;
        roff[t] = rowoff ? rowoff[r] : r * K;
    }
    __syncthreads();

    const int tx = t & 15;        // 0..15  -> col tile
    const int ty = t >> 4;        // 0..15  -> row tile

    const int arow  = t >> 1;     // 0..127
    const int akoff = (t & 1) * 4;

    float acc[TM][TN];
    #pragma unroll
    for (int i = 0; i < TM; i++)
        #pragma unroll
        for (int j = 0; j < TN; j++) acc[i][j] = 0.f;

    const int aro = roff[arow];
    const float* Bp = B + (size_t)(bn + arow) * K + akoff;

    for (int k0 = 0; k0 < K; k0 += BK) {
        float4 av = *(const float4*)(A + aro + k0 + akoff);
        float4 bv = *(const float4*)(Bp + k0);
        __syncthreads();   // previous tile fully consumed
        As[akoff + 0][arow] = av.x;
        As[akoff + 1][arow] = av.y;
        As[akoff + 2][arow] = av.z;
        As[akoff + 3][arow] = av.w;
        Bs[akoff + 0][arow] = bv.x;
        Bs[akoff + 1][arow] = bv.y;
        Bs[akoff + 2][arow] = bv.z;
        Bs[akoff + 3][arow] = bv.w;
        __syncthreads();

        #pragma unroll
        for (int k = 0; k < BK; k++) {
            float a[TM], b[TN];
            #pragma unroll
            for (int i = 0; i < TM; i++) a[i] = As[k][ty * TM + i];
            #pragma unroll
            for (int j = 0; j < TN; j++) b[j] = Bs[k][tx * TN + j];
            #pragma unroll
            for (int i = 0; i < TM; i++)
                #pragma unroll
                for (int j = 0; j < TN; j++)
                    acc[i][j] += a[i] * b[j];
        }
    }

    float bb[TN];
    #pragma unroll
    for (int j = 0; j < TN; j++)
        bb[j] = bias ? bias[bn + tx * TN + j] : 0.f;

    #pragma unroll
    for (int i = 0; i < TM; i++) {
        float* cp = C + (size_t)(bm + ty * TM + i) * ldc + bn + tx * TN;
        #pragma unroll
        for (int j = 0; j < TN; j++)
            cp[j] = acc[i][j] + bb[j];
    }
}

// ---------------------------------------------------------------------------
// Attention: one block per (group, head). 49x49 scores, softmax over k, @ V.
__global__ void __launch_bounds__(256)
attn_kernel(const float* __restrict__ kv, float* __restrict__ att)
{
    const int g = blockIdx.x;   // 0..1023
    const int h = blockIdx.y;   // 0..11

    __shared__ float Kh[PARTS][DH + 1];
    __shared__ float Vh[PARTS][DH + 1];
    __shared__ float S[PARTS][PARTS + 3];

    const int t = threadIdx.x;

    for (int i = t; i < PARTS * DH; i += 256) {
        int r = i >> 6, d = i & 63;
        const float* base = kv + (size_t)(g * PARTS + r) * 1536 + h * DH + d;
        Kh[r][d] = base[0];
        Vh[r][d] = base[768];
    }
    __syncthreads();

    for (int i = t; i < PARTS * PARTS; i += 256) {
        int q = i / PARTS, k = i % PARTS;
        float s = 0.f;
        #pragma unroll
        for (int d = 0; d < DH; d++) s += Kh[q][d] * Kh[k][d];
        S[q][k] = s * SCALE;
    }
    __syncthreads();

    if (t < PARTS) {
        float m = -1e30f;
        #pragma unroll
        for (int k = 0; k < PARTS; k++) m = fmaxf(m, S[t][k]);
        float sum = 0.f;
        #pragma unroll
        for (int k = 0; k < PARTS; k++) {
            float e = __expf(S[t][k] - m);
            S[t][k] = e;
            sum += e;
        }
        float inv = 1.f / sum;
        #pragma unroll
        for (int k = 0; k < PARTS; k++) S[t][k] *= inv;
    }
    __syncthreads();

    for (int i = t; i < PARTS * DH; i += 256) {
        int q = i >> 6, d = i & 63;
        float o = 0.f;
        #pragma unroll
        for (int k = 0; k < PARTS; k++) o += S[q][k] * Vh[k][d];
        att[(size_t)(g * PARTS + q) * DD + h * DH + d] = o;
    }
}

// ---------------------------------------------------------------------------
extern "C" void kernel_launch(void* const* d_in, const int* in_sizes, int n_in,
                              void* d_out, int out_size)
{
    const float* x      = (const float*)d_in[0];
    const float* w_qkv  = (const float*)d_in[1];
    const float* w_proj = (const float*)d_in[2];
    const float* b_proj = (const float*)d_in[3];
    const void*  sid    = d_in[4];
    float* out = (float*)d_out;

    float* kv;  cudaGetSymbolAddress((void**)&kv,  g_kv);
    float* att; cudaGetSymbolAddress((void**)&att, g_att);
    int* rowoff; cudaGetSymbolAddress((void**)&rowoff, g_rowoff);

    // 1. resolve shuffle_ids dtype + build gathered row offsets
    detect_idx_kernel<<<1, 1>>>(sid);
    rowoff_kernel<<<(ROWS + 255) / 256, 256>>>(sid);

    // 2. K,V projection with fused gather (skip dead Q): [50176,1536] = gather(x) @ Wkv^T
    {
        dim3 grid(1536 / BN, ROWS / BM);
        sgemm_nt<<<grid, 256>>>(x, rowoff, w_qkv + (size_t)DD * DD, nullptr,
                                kv, DD, 1536);
    }

    // 3. partitioned attention (q := k faithful-bug)
    {
        dim3 grid(GROUPS, HEADS);
        attn_kernel<<<grid, 256>>>(kv, att);
    }

    // 4. output projection + bias: [50176,768] = att @ Wproj^T + b
    {
        dim3 grid(DD / BN, ROWS / BM);
        sgemm_nt<<<grid, 256>>>(att, nullptr, w_proj, b_proj, out, DD, DD);
    }
}

// round 13
// speedup vs baseline: 2.4780x; 2.4780x over previous
#include <cuda_runtime.h>
#include <cstdint>

#define NB    32
#define LL    1568
#define DD    768
#define HEADS 12
#define PARTS 49
#define DH    64
#define ROWS  (NB * LL)          // 50176
#define GROUPS (ROWS / PARTS)    // 1024
#define SCALE 0.125f

__device__ float g_kv[(size_t)ROWS * 1536];
__device__ float g_att[(size_t)ROWS * DD];
__device__ int   g_rowoff[ROWS];
__device__ int   g_is64;

// ---------------------------------------------------------------------------
__global__ void detect_idx_kernel(const void* sid) {
    const unsigned* p = (const unsigned*)sid;
    int nz = 0;
    for (int i = 1; i < 2048; i += 2) nz += (p[i] != 0u);
    g_is64 = (nz == 0) ? 1 : 0;
}

__global__ void rowoff_kernel(const void* sid) {
    int r = blockIdx.x * 256 + threadIdx.x;
    if (r >= ROWS) return;
    int id;
    if (g_is64) id = (int)((const long long*)sid)[r];
    else        id = ((const int*)sid)[r];
    int n = r / LL;
    g_rowoff[r] = (n * LL + id) * DD;
}

// ---------------------------------------------------------------------------
// TF32 tensor-core NT GEMM: C[M,N] = gather(A) @ B^T (+bias)
// CTA tile 128x128x16, warp tile 64x32 (warps 2 in M x 4 in N), mma m16n8k8.
#define GBM 128
#define GBN 128
#define GBK 16
#define GST (GBK + 4)   // smem row stride 20 -> conflict-free fragment loads

__device__ __forceinline__ float to_tf32(float x) {
    unsigned u;
    asm volatile("cvt.rna.tf32.f32 %0, %1;" : "=r"(u) : "f"(x));
    return __uint_as_float(u);
}

__global__ void __launch_bounds__(256, 2)
gemm_tf32(const float* __restrict__ A, const int* __restrict__ rowoff,
          const float* __restrict__ B, const float* __restrict__ bias,
          float* __restrict__ C, int K, int ldc)
{
    __shared__ float As[GBM * GST];
    __shared__ float Bs[GBN * GST];
    __shared__ int   roff[GBM];

    const int t    = threadIdx.x;
    const int lane = t & 31;
    const int warp = t >> 5;
    const int bm = blockIdx.y * GBM;
    const int bn = blockIdx.x * GBN;

    const int wm = (warp & 1) * 64;   // warp M offset in CTA tile
    const int wn = (warp >> 1) * 32;  // warp N offset

    if (t < GBM) {
        int r = bm + t;
        roff[t] = rowoff ? rowoff[r] : r * K;
    }
    __syncthreads();

    // loader: 512 float4 chunks per matrix; this thread does chunks t and t+256
    const int r0 = t >> 2,  q0 = (t & 3) * 4;
    const int r1 = r0 + 64, q1 = q0;

    const float* a0p = A + roff[r0] + q0;
    const float* a1p = A + roff[r1] + q1;
    const float* b0p = B + (size_t)(bn + r0) * K + q0;
    const float* b1p = B + (size_t)(bn + r1) * K + q1;

    float acc[4][4][4];
    #pragma unroll
    for (int i = 0; i < 4; i++)
        #pragma unroll
        for (int j = 0; j < 4; j++)
            #pragma unroll
            for (int c = 0; c < 4; c++) acc[i][j][c] = 0.f;

    float4 av0 = *(const float4*)(a0p);
    float4 av1 = *(const float4*)(a1p);
    float4 bv0 = *(const float4*)(b0p);
    float4 bv1 = *(const float4*)(b1p);

    const int lq = lane >> 2;   // 0..7
    const int lr = lane & 3;    // 0..3

    for (int k0 = 0; k0 < K; k0 += GBK) {
        __syncthreads();
        As[r0 * GST + q0 + 0] = to_tf32(av0.x);
        As[r0 * GST + q0 + 1] = to_tf32(av0.y);
        As[r0 * GST + q0 + 2] = to_tf32(av0.z);
        As[r0 * GST + q0 + 3] = to_tf32(av0.w);
        As[r1 * GST + q1 + 0] = to_tf32(av1.x);
        As[r1 * GST + q1 + 1] = to_tf32(av1.y);
        As[r1 * GST + q1 + 2] = to_tf32(av1.z);
        As[r1 * GST + q1 + 3] = to_tf32(av1.w);
        Bs[r0 * GST + q0 + 0] = to_tf32(bv0.x);
        Bs[r0 * GST + q0 + 1] = to_tf32(bv0.y);
        Bs[r0 * GST + q0 + 2] = to_tf32(bv0.z);
        Bs[r0 * GST + q0 + 3] = to_tf32(bv0.w);
        Bs[r1 * GST + q1 + 0] = to_tf32(bv1.x);
        Bs[r1 * GST + q1 + 1] = to_tf32(bv1.y);
        Bs[r1 * GST + q1 + 2] = to_tf32(bv1.z);
        Bs[r1 * GST + q1 + 3] = to_tf32(bv1.w);
        __syncthreads();

        // prefetch next gmem tile while computing this one
        if (k0 + GBK < K) {
            av0 = *(const float4*)(a0p + k0 + GBK);
            av1 = *(const float4*)(a1p + k0 + GBK);
            bv0 = *(const float4*)(b0p + k0 + GBK);
            bv1 = *(const float4*)(b1p + k0 + GBK);
        }

        #pragma unroll
        for (int ks = 0; ks < GBK; ks += 8) {
            unsigned af[4][4], bf[4][2];
            #pragma unroll
            for (int i = 0; i < 4; i++) {
                int m = wm + i * 16 + lq;
                af[i][0] = __float_as_uint(As[(m    ) * GST + ks + lr    ]);
                af[i][1] = __float_as_uint(As[(m + 8) * GST + ks + lr    ]);
                af[i][2] = __float_as_uint(As[(m    ) * GST + ks + lr + 4]);
                af[i][3] = __float_as_uint(As[(m + 8) * GST + ks + lr + 4]);
            }
            #pragma unroll
            for (int j = 0; j < 4; j++) {
                int n = wn + j * 8 + lq;
                bf[j][0] = __float_as_uint(Bs[n * GST + ks + lr    ]);
                bf[j][1] = __float_as_uint(Bs[n * GST + ks + lr + 4]);
            }
            #pragma unroll
            for (int i = 0; i < 4; i++)
                #pragma unroll
                for (int j = 0; j < 4; j++) {
                    asm volatile(
                        "mma.sync.aligned.m16n8k8.row.col.f32.tf32.tf32.f32 "
                        "{%0,%1,%2,%3}, {%4,%5,%6,%7}, {%8,%9}, {%0,%1,%2,%3};"
                        : "+f"(acc[i][j][0]), "+f"(acc[i][j][1]),
                          "+f"(acc[i][j][2]), "+f"(acc[i][j][3])
                        : "r"(af[i][0]), "r"(af[i][1]), "r"(af[i][2]), "r"(af[i][3]),
                          "r"(bf[j][0]), "r"(bf[j][1]));
                }
        }
    }

    // epilogue
    #pragma unroll
    for (int i = 0; i < 4; i++) {
        int row0 = bm + wm + i * 16 + lq;
        #pragma unroll
        for (int j = 0; j < 4; j++) {
            int col = bn + wn + j * 8 + 2 * lr;
            float b0 = bias ? bias[col]     : 0.f;
            float b1 = bias ? bias[col + 1] : 0.f;
            float2 v0 = make_float2(acc[i][j][0] + b0, acc[i][j][1] + b1);
            float2 v1 = make_float2(acc[i][j][2] + b0, acc[i][j][3] + b1);
            *(float2*)(C + (size_t)row0 * ldc + col)       = v0;
            *(float2*)(C + (size_t)(row0 + 8) * ldc + col) = v1;
        }
    }
}

// ---------------------------------------------------------------------------
// Attention: one block per (group, head). Register-tiled 4x4 per thread.
__global__ void __launch_bounds__(256)
attn_kernel(const float* __restrict__ kv, float* __restrict__ att)
{
    const int g = blockIdx.x;
    const int h = blockIdx.y;

    __shared__ float Kh[64][DH + 1];
    __shared__ float Vh[64][DH + 1];
    __shared__ float S[64][68];   // full padded 64x64 tile + 4 pad (was [64][52]: OOB -> IMA)

    const int t  = threadIdx.x;
    const int tx = t & 15;
    const int ty = t >> 4;

    for (int i = t; i < 64 * DH; i += 256) {
        int r = i >> 6, d = i & 63;
        if (r < PARTS) {
            const float* base = kv + (size_t)(g * PARTS + r) * 1536 + h * DH + d;
            Kh[r][d] = base[0];
            Vh[r][d] = base[768];
        } else {
            Kh[r][d] = 0.f;
            Vh[r][d] = 0.f;
        }
    }
    __syncthreads();

    // S = (K K^T) * SCALE, 4x4 per thread over padded 64x64
    {
        const int q0 = ty * 4, k0 = tx * 4;
        float acc[4][4];
        #pragma unroll
        for (int i = 0; i < 4; i++)
            #pragma unroll
            for (int j = 0; j < 4; j++) acc[i][j] = 0.f;
        #pragma unroll 8
        for (int d = 0; d < DH; d++) {
            float a[4], b[4];
            #pragma unroll
            for (int i = 0; i < 4; i++) a[i] = Kh[q0 + i][d];
            #pragma unroll
            for (int j = 0; j < 4; j++) b[j] = Kh[k0 + j][d];
            #pragma unroll
            for (int i = 0; i < 4; i++)
                #pragma unroll
                for (int j = 0; j < 4; j++) acc[i][j] += a[i] * b[j];
        }
        #pragma unroll
        for (int i = 0; i < 4; i++)
            #pragma unroll
            for (int j = 0; j < 4; j++)
                S[q0 + i][k0 + j] = acc[i][j] * SCALE;
    }
    __syncthreads();

    // softmax over k (only k < 49 valid)
    if (t < PARTS) {
        float m = -1e30f;
        #pragma unroll
        for (int k = 0; k < PARTS; k++) m = fmaxf(m, S[t][k]);
        float sum = 0.f;
        #pragma unroll
        for (int k = 0; k < PARTS; k++) {
            float e = __expf(S[t][k] - m);
            S[t][k] = e;
            sum += e;
        }
        float inv = 1.f / sum;
        #pragma unroll
        for (int k = 0; k < PARTS; k++) S[t][k] *= inv;
    }
    __syncthreads();

    // out = S @ V, 4x4 per thread over (q,d) in 64x64
    {
        const int q0 = ty * 4, d0 = tx * 4;
        float acc[4][4];
        #pragma unroll
        for (int i = 0; i < 4; i++)
            #pragma unroll
            for (int j = 0; j < 4; j++) acc[i][j] = 0.f;
        #pragma unroll 7
        for (int k = 0; k < PARTS; k++) {
            float a[4], b[4];
            #pragma unroll
            for (int i = 0; i < 4; i++) a[i] = S[q0 + i][k];
            #pragma unroll
            for (int j = 0; j < 4; j++) b[j] = Vh[k][d0 + j];
            #pragma unroll
            for (int i = 0; i < 4; i++)
                #pragma unroll
                for (int j = 0; j < 4; j++) acc[i][j] += a[i] * b[j];
        }
        #pragma unroll
        for (int i = 0; i < 4; i++) {
            int q = q0 + i;
            if (q < PARTS) {
                float* op = att + (size_t)(g * PARTS + q) * DD + h * DH + d0;
                #pragma unroll
                for (int j = 0; j < 4; j++) op[j] = acc[i][j];
            }
        }
    }
}

// ---------------------------------------------------------------------------
extern "C" void kernel_launch(void* const* d_in, const int* in_sizes, int n_in,
                              void* d_out, int out_size)
{
    const float* x      = (const float*)d_in[0];
    const float* w_qkv  = (const float*)d_in[1];
    const float* w_proj = (const float*)d_in[2];
    const float* b_proj = (const float*)d_in[3];
    const void*  sid    = d_in[4];
    float* out = (float*)d_out;

    float* kv;  cudaGetSymbolAddress((void**)&kv,  g_kv);
    float* att; cudaGetSymbolAddress((void**)&att, g_att);
    int* rowoff; cudaGetSymbolAddress((void**)&rowoff, g_rowoff);

    detect_idx_kernel<<<1, 1>>>(sid);
    rowoff_kernel<<<(ROWS + 255) / 256, 256>>>(sid);

    // K,V projection with fused gather (Q is dead): [50176,1536]
    {
        dim3 grid(1536 / GBN, ROWS / GBM);
        gemm_tf32<<<grid, 256>>>(x, rowoff, w_qkv + (size_t)DD * DD, nullptr,
                                 kv, DD, 1536);
    }

    // partitioned attention
    {
        dim3 grid(GROUPS, HEADS);
        attn_kernel<<<grid, 256>>>(kv, att);
    }

    // output projection + bias: [50176,768]
    {
        dim3 grid(DD / GBN, ROWS / GBM);
        gemm_tf32<<<grid, 256>>>(att, nullptr, w_proj, b_proj, out, DD, DD);
    }
}

// round 16
// speedup vs baseline: 2.6987x; 1.0891x over previous
#include <cuda_runtime.h>
#include <cstdint>

#define NB    32
#define LL    1568
#define DD    768
#define HEADS 12
#define PARTS 49
#define DH    64
#define ROWS  (NB * LL)          // 50176
#define GROUPS (ROWS / PARTS)    // 1024
#define SCALE 0.125f

__device__ float g_kv[(size_t)ROWS * 1536];
__device__ float g_att[(size_t)ROWS * DD];
__device__ int   g_rowoff[ROWS];
__device__ int   g_is64;

// ---------------------------------------------------------------------------
__global__ void detect_idx_kernel(const void* sid) {
    const unsigned* p = (const unsigned*)sid;
    int nz = 0;
    for (int i = 1; i < 2048; i += 2) nz += (p[i] != 0u);
    g_is64 = (nz == 0) ? 1 : 0;
}

__global__ void rowoff_kernel(const void* sid) {
    int r = blockIdx.x * 256 + threadIdx.x;
    if (r >= ROWS) return;
    int id;
    if (g_is64) id = (int)((const long long*)sid)[r];
    else        id = ((const int*)sid)[r];
    int n = r / LL;
    g_rowoff[r] = (n * LL + id) * DD;
}

// ---------------------------------------------------------------------------
// TF32 tensor-core NT GEMM: C[M,N] = gather(A) @ B^T (+bias)
// CTA tile 128x128x16, warp tile 64x32 (warps 2 in M x 4 in N), mma m16n8k8.
#define GBM 128
#define GBN 128
#define GBK 16
#define GST (GBK + 4)   // smem row stride 20 -> conflict-free fragment loads

__device__ __forceinline__ float to_tf32(float x) {
    unsigned u;
    asm volatile("cvt.rna.tf32.f32 %0, %1;" : "=r"(u) : "f"(x));
    return __uint_as_float(u);
}

__global__ void __launch_bounds__(256, 2)
gemm_tf32(const float* __restrict__ A, const int* __restrict__ rowoff,
          const float* __restrict__ B, const float* __restrict__ bias,
          float* __restrict__ C, int K, int ldc)
{
    __shared__ float As[GBM * GST];
    __shared__ float Bs[GBN * GST];
    __shared__ int   roff[GBM];

    const int t    = threadIdx.x;
    const int lane = t & 31;
    const int warp = t >> 5;
    const int bm = blockIdx.y * GBM;
    const int bn = blockIdx.x * GBN;

    const int wm = (warp & 1) * 64;   // warp M offset in CTA tile
    const int wn = (warp >> 1) * 32;  // warp N offset

    if (t < GBM) {
        int r = bm + t;
        roff[t] = rowoff ? rowoff[r] : r * K;
    }
    __syncthreads();

    // loader: 512 float4 chunks per matrix; this thread does chunks t and t+256
    const int r0 = t >> 2,  q0 = (t & 3) * 4;
    const int r1 = r0 + 64, q1 = q0;

    const float* a0p = A + roff[r0] + q0;
    const float* a1p = A + roff[r1] + q1;
    const float* b0p = B + (size_t)(bn + r0) * K + q0;
    const float* b1p = B + (size_t)(bn + r1) * K + q1;

    float acc[4][4][4];
    #pragma unroll
    for (int i = 0; i < 4; i++)
        #pragma unroll
        for (int j = 0; j < 4; j++)
            #pragma unroll
            for (int c = 0; c < 4; c++) acc[i][j][c] = 0.f;

    float4 av0 = *(const float4*)(a0p);
    float4 av1 = *(const float4*)(a1p);
    float4 bv0 = *(const float4*)(b0p);
    float4 bv1 = *(const float4*)(b1p);

    const int lq = lane >> 2;   // 0..7
    const int lr = lane & 3;    // 0..3

    for (int k0 = 0; k0 < K; k0 += GBK) {
        __syncthreads();
        As[r0 * GST + q0 + 0] = to_tf32(av0.x);
        As[r0 * GST + q0 + 1] = to_tf32(av0.y);
        As[r0 * GST + q0 + 2] = to_tf32(av0.z);
        As[r0 * GST + q0 + 3] = to_tf32(av0.w);
        As[r1 * GST + q1 + 0] = to_tf32(av1.x);
        As[r1 * GST + q1 + 1] = to_tf32(av1.y);
        As[r1 * GST + q1 + 2] = to_tf32(av1.z);
        As[r1 * GST + q1 + 3] = to_tf32(av1.w);
        Bs[r0 * GST + q0 + 0] = to_tf32(bv0.x);
        Bs[r0 * GST + q0 + 1] = to_tf32(bv0.y);
        Bs[r0 * GST + q0 + 2] = to_tf32(bv0.z);
        Bs[r0 * GST + q0 + 3] = to_tf32(bv0.w);
        Bs[r1 * GST + q1 + 0] = to_tf32(bv1.x);
        Bs[r1 * GST + q1 + 1] = to_tf32(bv1.y);
        Bs[r1 * GST + q1 + 2] = to_tf32(bv1.z);
        Bs[r1 * GST + q1 + 3] = to_tf32(bv1.w);
        __syncthreads();

        // prefetch next gmem tile while computing this one
        if (k0 + GBK < K) {
            av0 = *(const float4*)(a0p + k0 + GBK);
            av1 = *(const float4*)(a1p + k0 + GBK);
            bv0 = *(const float4*)(b0p + k0 + GBK);
            bv1 = *(const float4*)(b1p + k0 + GBK);
        }

        #pragma unroll
        for (int ks = 0; ks < GBK; ks += 8) {
            unsigned af[4][4], bf[4][2];
            #pragma unroll
            for (int i = 0; i < 4; i++) {
                int m = wm + i * 16 + lq;
                af[i][0] = __float_as_uint(As[(m    ) * GST + ks + lr    ]);
                af[i][1] = __float_as_uint(As[(m + 8) * GST + ks + lr    ]);
                af[i][2] = __float_as_uint(As[(m    ) * GST + ks + lr + 4]);
                af[i][3] = __float_as_uint(As[(m + 8) * GST + ks + lr + 4]);
            }
            #pragma unroll
            for (int j = 0; j < 4; j++) {
                int n = wn + j * 8 + lq;
                bf[j][0] = __float_as_uint(Bs[n * GST + ks + lr    ]);
                bf[j][1] = __float_as_uint(Bs[n * GST + ks + lr + 4]);
            }
            #pragma unroll
            for (int i = 0; i < 4; i++)
                #pragma unroll
                for (int j = 0; j < 4; j++) {
                    asm volatile(
                        "mma.sync.aligned.m16n8k8.row.col.f32.tf32.tf32.f32 "
                        "{%0,%1,%2,%3}, {%4,%5,%6,%7}, {%8,%9}, {%0,%1,%2,%3};"
                        : "+f"(acc[i][j][0]), "+f"(acc[i][j][1]),
                          "+f"(acc[i][j][2]), "+f"(acc[i][j][3])
                        : "r"(af[i][0]), "r"(af[i][1]), "r"(af[i][2]), "r"(af[i][3]),
                          "r"(bf[j][0]), "r"(bf[j][1]));
                }
        }
    }

    // epilogue
    #pragma unroll
    for (int i = 0; i < 4; i++) {
        int row0 = bm + wm + i * 16 + lq;
        #pragma unroll
        for (int j = 0; j < 4; j++) {
            int col = bn + wn + j * 8 + 2 * lr;
            float b0 = bias ? bias[col]     : 0.f;
            float b1 = bias ? bias[col + 1] : 0.f;
            float2 v0 = make_float2(acc[i][j][0] + b0, acc[i][j][1] + b1);
            float2 v1 = make_float2(acc[i][j][2] + b0, acc[i][j][3] + b1);
            *(float2*)(C + (size_t)row0 * ldc + col)       = v0;
            *(float2*)(C + (size_t)(row0 + 8) * ldc + col) = v1;
        }
    }
}

// ---------------------------------------------------------------------------
// Attention: one block per (group, head). 4x4 register tile per thread with
// ALL inner-loop smem traffic vectorized/contiguous:
//   Kd[d][r]  - K transposed  -> S-phase: 2x LDS.128 per d
//   St[k][q]  - S transposed  -> PV-phase: broadcast LDS.128 + LDS.128 per k
//   Vh[r][d]  - V row-major   -> PV-phase float4
#define AST 68   // shared row stride (words), multiple of 4 for float4
__global__ void __launch_bounds__(256)
attn_kernel(const float* __restrict__ kv, float* __restrict__ att)
{
    const int g = blockIdx.x;
    const int h = blockIdx.y;

    __shared__ float Kd[DH][AST];   // [d][row]
    __shared__ float Vh[64][AST];   // [row][d]
    __shared__ float St[64][AST];   // [k][q]

    const int t  = threadIdx.x;
    const int tx = t & 15;
    const int ty = t >> 4;

    // load K (transposed) and V (row-major) with float4 gmem reads
    for (int i = t; i < PARTS * 16; i += 256) {        // 784 float4 per matrix
        int r  = i >> 4;
        int c4 = (i & 15) * 4;
        const float* base = kv + (size_t)(g * PARTS + r) * 1536 + h * DH + c4;
        float4 kvv = *(const float4*)(base);
        float4 vvv = *(const float4*)(base + 768);
        Kd[c4 + 0][r] = kvv.x;
        Kd[c4 + 1][r] = kvv.y;
        Kd[c4 + 2][r] = kvv.z;
        Kd[c4 + 3][r] = kvv.w;
        *(float4*)&Vh[r][c4] = vvv;
    }
    // zero-fill padded rows 49..63
    for (int i = t; i < (64 - PARTS) * 16; i += 256) {
        int r  = PARTS + (i >> 4);
        int c4 = (i & 15) * 4;
        Kd[c4 + 0][r] = 0.f;
        Kd[c4 + 1][r] = 0.f;
        Kd[c4 + 2][r] = 0.f;
        Kd[c4 + 3][r] = 0.f;
        *(float4*)&Vh[r][c4] = make_float4(0.f, 0.f, 0.f, 0.f);
    }
    __syncthreads();

    // S^T = (K K^T)*SCALE, stored transposed: St[k][q]
    {
        const int q0 = ty * 4, k0 = tx * 4;
        float acc[4][4];
        #pragma unroll
        for (int i = 0; i < 4; i++)
            #pragma unroll
            for (int j = 0; j < 4; j++) acc[i][j] = 0.f;
        #pragma unroll 4
        for (int d = 0; d < DH; d++) {
            float4 a4 = *(const float4*)&Kd[d][q0];
            float4 b4 = *(const float4*)&Kd[d][k0];
            float a[4] = {a4.x, a4.y, a4.z, a4.w};
            float b[4] = {b4.x, b4.y, b4.z, b4.w};
            #pragma unroll
            for (int i = 0; i < 4; i++)
                #pragma unroll
                for (int j = 0; j < 4; j++) acc[i][j] += a[i] * b[j];
        }
        #pragma unroll
        for (int i = 0; i < 4; i++)
            #pragma unroll
            for (int j = 0; j < 4; j++)
                St[k0 + j][q0 + i] = acc[i][j] * SCALE;
    }
    __syncthreads();

    // softmax over k for each valid q row: St[k][q], k stride AST
    if (t < PARTS) {
        float m = -1e30f;
        #pragma unroll
        for (int k = 0; k < PARTS; k++) m = fmaxf(m, St[k][t]);
        float sum = 0.f;
        #pragma unroll
        for (int k = 0; k < PARTS; k++) {
            float e = __expf(St[k][t] - m);
            St[k][t] = e;
            sum += e;
        }
        float inv = 1.f / sum;
        #pragma unroll
        for (int k = 0; k < PARTS; k++) St[k][t] *= inv;
    }
    __syncthreads();

    // out = S @ V : acc[q][d] over k; a from St[k][q0..] (broadcast), b from Vh[k][d0..]
    {
        const int q0 = ty * 4, d0 = tx * 4;
        float acc[4][4];
        #pragma unroll
        for (int i = 0; i < 4; i++)
            #pragma unroll
            for (int j = 0; j < 4; j++) acc[i][j] = 0.f;
        #pragma unroll 7
        for (int k = 0; k < PARTS; k++) {
            float4 a4 = *(const float4*)&St[k][q0];
            float4 b4 = *(const float4*)&Vh[k][d0];
            float a[4] = {a4.x, a4.y, a4.z, a4.w};
            float b[4] = {b4.x, b4.y, b4.z, b4.w};
            #pragma unroll
            for (int i = 0; i < 4; i++)
                #pragma unroll
                for (int j = 0; j < 4; j++) acc[i][j] += a[i] * b[j];
        }
        #pragma unroll
        for (int i = 0; i < 4; i++) {
            int q = q0 + i;
            if (q < PARTS) {
                float* op = att + (size_t)(g * PARTS + q) * DD + h * DH + d0;
                *(float4*)op = make_float4(acc[i][0], acc[i][1], acc[i][2], acc[i][3]);
            }
        }
    }
}

// ---------------------------------------------------------------------------
extern "C" void kernel_launch(void* const* d_in, const int* in_sizes, int n_in,
                              void* d_out, int out_size)
{
    const float* x      = (const float*)d_in[0];
    const float* w_qkv  = (const float*)d_in[1];
    const float* w_proj = (const float*)d_in[2];
    const float* b_proj = (const float*)d_in[3];
    const void*  sid    = d_in[4];
    float* out = (float*)d_out;

    float* kv;  cudaGetSymbolAddress((void**)&kv,  g_kv);
    float* att; cudaGetSymbolAddress((void**)&att, g_att);
    int* rowoff; cudaGetSymbolAddress((void**)&rowoff, g_rowoff);

    detect_idx_kernel<<<1, 1>>>(sid);
    rowoff_kernel<<<(ROWS + 255) / 256, 256>>>(sid);

    // K,V projection with fused gather (Q is dead): [50176,1536]
    {
        dim3 grid(1536 / GBN, ROWS / GBM);
        gemm_tf32<<<grid, 256>>>(x, rowoff, w_qkv + (size_t)DD * DD, nullptr,
                                 kv, DD, 1536);
    }

    // partitioned attention
    {
        dim3 grid(GROUPS, HEADS);
        attn_kernel<<<grid, 256>>>(kv, att);
    }

    // output projection + bias: [50176,768]
    {
        dim3 grid(DD / GBN, ROWS / GBM);
        gemm_tf32<<<grid, 256>>>(att, nullptr, w_proj, b_proj, out, DD, DD);
    }
}